// round 12
// baseline (speedup 1.0000x reference)
#include <cuda_runtime.h>
#include <cuda_bf16.h>
#include <math.h>
#include <stdint.h>

#define HH      148
#define WWIDTH  300
#define HWPIX   44400      // 148*300
#define DDIM    128
#define MKEYS   2048
#define NBLK_PIX 174       // ceil(44400/256)
#define WSLOT   1179648    // max weight elems per net slot (256*512*9)

// ---------------- scratch (device globals; no allocation allowed) -----------
__device__ float g_qn[DDIM * HWPIX];          // normalized query, planar [c][p]
__device__ float g_qnn[HWPIX];
__device__ float g_mn[MKEYS];
__device__ float g_cos[(size_t)MKEYS * HWPIX];// 364 MB
__device__ float g_L[MKEYS];
__device__ int   g_i1[HWPIX];
__device__ int   g_i2[HWPIX];
__device__ float g_av[64 * HWPIX];            // a = theta_net(qn, k_w*), planar
__device__ float g_bv[64 * HWPIX];            // b = theta_net(qn, t_w*), planar
__device__ float g_partG[NBLK_PIX];
__device__ float g_partS[NBLK_PIX];

// bf16 split activations, NHWC [pixel][ch]; per-net blocks for hidden layers
__device__ __nv_bfloat16 g_q_hi[(size_t)DDIM * HWPIX];
__device__ __nv_bfloat16 g_q_lo[(size_t)DDIM * HWPIX];
__device__ __nv_bfloat16 g_h1_hi[(size_t)2 * 512 * HWPIX];
__device__ __nv_bfloat16 g_h1_lo[(size_t)2 * 512 * HWPIX];
__device__ __nv_bfloat16 g_h2_hi[(size_t)2 * 256 * HWPIX];
__device__ __nv_bfloat16 g_h2_lo[(size_t)2 * 256 * HWPIX];
__device__ __nv_bfloat16 g_h3_hi[(size_t)2 * 128 * HWPIX];
__device__ __nv_bfloat16 g_h3_lo[(size_t)2 * 128 * HWPIX];
// bf16 split weights [net][tap][oc][c]
__device__ __nv_bfloat16 g_w_hi[(size_t)2 * WSLOT];
__device__ __nv_bfloat16 g_w_lo[(size_t)2 * WSLOT];
// bf16 split keys [m][k]
__device__ __nv_bfloat16 g_k_hi[MKEYS * DDIM];
__device__ __nv_bfloat16 g_k_lo[MKEYS * DDIM];

// ---------------- warp MMA + cp.async helpers --------------------------------
__device__ __forceinline__ uint32_t smem_u32(const void* p) {
    uint32_t a;
    asm("{ .reg .u64 t; cvta.to.shared.u64 t, %1; cvt.u32.u64 %0, t; }"
        : "=r"(a) : "l"(p));
    return a;
}
__device__ __forceinline__ void ldm_x4(uint32_t* r, uint32_t addr) {
    asm volatile("ldmatrix.sync.aligned.m8n8.x4.shared.b16 {%0,%1,%2,%3}, [%4];"
                 : "=r"(r[0]), "=r"(r[1]), "=r"(r[2]), "=r"(r[3]) : "r"(addr));
}
__device__ __forceinline__ void mma16816(float* d, const uint32_t* a, const uint32_t* b) {
    asm volatile("mma.sync.aligned.m16n8k16.row.col.f32.bf16.bf16.f32 "
                 "{%0,%1,%2,%3}, {%4,%5,%6,%7}, {%8,%9}, {%0,%1,%2,%3};"
                 : "+f"(d[0]), "+f"(d[1]), "+f"(d[2]), "+f"(d[3])
                 : "r"(a[0]), "r"(a[1]), "r"(a[2]), "r"(a[3]),
                   "r"(b[0]), "r"(b[1]));
}
__device__ __forceinline__ void cp16(uint32_t dst, const void* src, int srcbytes) {
    asm volatile("cp.async.cg.shared.global [%0], [%1], 16, %2;"
                 :: "r"(dst), "l"(src), "r"(srcbytes));
}
#define CP_COMMIT() asm volatile("cp.async.commit_group;" ::: "memory")
#define CP_WAIT0()  asm volatile("cp.async.wait_group 0;" ::: "memory")
#define CP_WAIT1()  asm volatile("cp.async.wait_group 1;" ::: "memory")

// ---------------- query normalize (planar fp32 + NHWC bf16 hi/lo) ------------
__global__ __launch_bounds__(256) void qnorm_kernel(const float* __restrict__ q)
{
    int p = blockIdx.x * 256 + threadIdx.x;
    if (p >= HWPIX) return;
    float s = 0.f;
    #pragma unroll 4
    for (int c = 0; c < DDIM; ++c) { float v = q[c * HWPIX + p]; s = fmaf(v, v, s); }
    float r = sqrtf(s);
    float inv = 1.f / fmaxf(r, 1e-12f);
    #pragma unroll 4
    for (int c = 0; c < DDIM; ++c) {
        float v = q[c * HWPIX + p] * inv;
        g_qn[c * HWPIX + p] = v;
        __nv_bfloat16 h = __float2bfloat16(v);
        g_q_hi[(size_t)p * DDIM + c] = h;
        g_q_lo[(size_t)p * DDIM + c] = __float2bfloat16(v - __bfloat162float(h));
    }
    g_qnn[p] = r * inv;
}

// ---------------- key norms + bf16 split -------------------------------------
__global__ void keynorm_kernel(const float* __restrict__ keys)
{
    int m = blockIdx.x * 8 + (threadIdx.x >> 5);
    int lane = threadIdx.x & 31;
    float s = 0.f;
    for (int j = lane; j < DDIM; j += 32) {
        float v = keys[m * DDIM + j];
        s = fmaf(v, v, s);
        __nv_bfloat16 h = __float2bfloat16(v);
        g_k_hi[m * DDIM + j] = h;
        g_k_lo[m * DDIM + j] = __float2bfloat16(v - __bfloat162float(h));
    }
    #pragma unroll
    for (int o = 16; o > 0; o >>= 1) s += __shfl_xor_sync(0xffffffffu, s, o);
    if (lane == 0) g_mn[m] = sqrtf(s);
}

// ---------------- score GEMM via mma.sync (3-pass bf16 split) ----------------
__global__ __launch_bounds__(256) void score_mma_kernel()
{
    __shared__ __align__(16) __nv_bfloat16 sA[2][128][40];  // keys [plane][m][k]
    __shared__ __align__(16) __nv_bfloat16 sB[2][64][40];   // pixels [plane][n][k]

    const int tid  = threadIdx.x;
    const int lane = tid & 31;
    const int wid  = tid >> 5;
    const int warpM = wid & 3;
    const int warpN = wid >> 2;
    const int m0 = blockIdx.y * 128;
    const int n0 = blockIdx.x * 64;

    float c_acc[2][4][4];
    #pragma unroll
    for (int i = 0; i < 2; ++i)
        #pragma unroll
        for (int j = 0; j < 4; ++j)
            #pragma unroll
            for (int k = 0; k < 4; ++k) c_acc[i][j][k] = 0.f;

    const int lr = lane & 15, lc = lane >> 4;
    const int bg = lane >> 3, br = lane & 7;

    for (int ch = 0; ch < 4; ++ch) {
        const int c0 = ch * 32;
        if (ch) __syncthreads();
        #pragma unroll
        for (int s = 0; s < 4; ++s) {
            int idx = tid + s * 256;
            int plane = idx >> 9;
            int m = (idx >> 2) & 127;
            int j = idx & 3;
            uint4 v = *(const uint4*)((plane ? g_k_lo : g_k_hi) +
                                      (size_t)(m0 + m) * DDIM + c0 + j * 8);
            *(uint4*)&sA[plane][m][j * 8] = v;
        }
        #pragma unroll
        for (int s = 0; s < 2; ++s) {
            int idx = tid + s * 256;
            int plane = idx >> 8;
            int n = (idx >> 2) & 63;
            int j = idx & 3;
            uint4 v = make_uint4(0u, 0u, 0u, 0u);
            if (n0 + n < HWPIX)
                v = *(const uint4*)((plane ? g_q_lo : g_q_hi) +
                                    (size_t)(n0 + n) * DDIM + c0 + j * 8);
            *(uint4*)&sB[plane][n][j * 8] = v;
        }
        __syncthreads();

        #pragma unroll
        for (int ks = 0; ks < 2; ++ks) {
            uint32_t aH[2][4], aL[2][4];
            #pragma unroll
            for (int i = 0; i < 2; ++i) {
                ldm_x4(aH[i], smem_u32(&sA[0][warpM * 32 + i * 16 + lr][ks * 16 + lc * 8]));
                ldm_x4(aL[i], smem_u32(&sA[1][warpM * 32 + i * 16 + lr][ks * 16 + lc * 8]));
            }
            uint32_t bH[4][2], bL[4][2];
            #pragma unroll
            for (int nb = 0; nb < 2; ++nb) {
                uint32_t t4[4];
                int row = warpN * 32 + nb * 16 + (bg >> 1) * 8 + br;
                int col = ks * 16 + (bg & 1) * 8;
                ldm_x4(t4, smem_u32(&sB[0][row][col]));
                bH[nb * 2][0] = t4[0]; bH[nb * 2][1] = t4[1];
                bH[nb * 2 + 1][0] = t4[2]; bH[nb * 2 + 1][1] = t4[3];
                ldm_x4(t4, smem_u32(&sB[1][row][col]));
                bL[nb * 2][0] = t4[0]; bL[nb * 2][1] = t4[1];
                bL[nb * 2 + 1][0] = t4[2]; bL[nb * 2 + 1][1] = t4[3];
            }
            #pragma unroll
            for (int i = 0; i < 2; ++i)
                #pragma unroll
                for (int j = 0; j < 4; ++j) {
                    mma16816(c_acc[i][j], aH[i], bH[j]);
                    mma16816(c_acc[i][j], aH[i], bL[j]);
                    mma16816(c_acc[i][j], aL[i], bH[j]);
                }
        }
    }

    const int q = lane >> 2;
    const int n2 = (lane & 3) * 2;
    #pragma unroll
    for (int i = 0; i < 2; ++i) {
        #pragma unroll
        for (int h = 0; h < 2; ++h) {
            int m = m0 + warpM * 32 + i * 16 + q + h * 8;
            float mnv = __ldg(&g_mn[m]);
            #pragma unroll
            for (int j = 0; j < 4; ++j) {
                int n = n0 + warpN * 32 + j * 8 + n2;
                if (n < HWPIX) {
                    float q0 = __ldg(&g_qnn[n]);
                    float q1 = __ldg(&g_qnn[n + 1]);
                    float2 w;
                    w.x = c_acc[i][j][h * 2 + 0] / fmaxf(mnv * q0, 1e-6f);
                    w.y = c_acc[i][j][h * 2 + 1] / fmaxf(mnv * q1, 1e-6f);
                    *(float2*)&g_cos[(size_t)m * HWPIX + n] = w;
                }
            }
        }
    }
}

// ---------------- per-row logsumexp ------------------------------------------
__global__ __launch_bounds__(256) void rowsum_kernel()
{
    __shared__ float sred[256];
    const float* cp = g_cos + (size_t)blockIdx.x * HWPIX;
    float s = 0.f;
    for (int n = threadIdx.x; n < HWPIX; n += 256) s += expf(cp[n]);
    sred[threadIdx.x] = s;
    __syncthreads();
    for (int k = 128; k > 0; k >>= 1) {
        if (threadIdx.x < k) sred[threadIdx.x] += sred[threadIdx.x + k];
        __syncthreads();
    }
    if (threadIdx.x == 0) g_L[blockIdx.x] = logf(sred[0]);
}

// ---------------- per-pixel top-2 of (cos[m,n] - L[m]) -----------------------
__global__ __launch_bounds__(256) void top2_kernel()
{
    __shared__ float sL[MKEYS];
    for (int i = threadIdx.x; i < MKEYS; i += 256) sL[i] = g_L[i];
    __syncthreads();
    int n = blockIdx.x * 256 + threadIdx.x;
    if (n >= HWPIX) return;
    float v1 = -1e30f, v2 = -1e30f;
    int i1 = 0, i2 = 0;
    const float* cp = g_cos + n;
    #pragma unroll 4
    for (int m = 0; m < MKEYS; ++m) {
        float s = cp[(size_t)m * HWPIX] - sL[m];
        if (s > v1)      { v2 = v1; i2 = i1; v1 = s; i1 = m; }
        else if (s > v2) { v2 = s; i2 = m; }
    }
    g_i1[n] = i1;
    g_i2[n] = i2;
}

// ---------------- losses (with reference's top2.T.reshape scrambling) --------
__global__ __launch_bounds__(256) void loss_kernel(const float* __restrict__ keys)
{
    __shared__ float sg[256], ss[256];
    int n = blockIdx.x * 256 + threadIdx.x;
    float ag = 0.f, asprd = 0.f;
    if (n < HWPIX) {
        int gi = g_i1[n];
        int pos_idx, neg_idx;
        if (n < HWPIX / 2) {
            pos_idx = g_i1[2 * n];
            neg_idx = g_i1[2 * n + 1];
        } else {
            int m2 = n - HWPIX / 2;
            pos_idx = g_i2[2 * m2];
            neg_idx = g_i2[2 * m2 + 1];
        }
        const float* kg = keys + (size_t)gi * DDIM;
        const float* kp = keys + (size_t)pos_idx * DDIM;
        const float* kn = keys + (size_t)neg_idx * DDIM;
        float s_g = 0.f, s_p = 0.f, s_n = 0.f;
        #pragma unroll 4
        for (int d = 0; d < DDIM; ++d) {
            float qv = g_qn[d * HWPIX + n];
            float a1 = qv - __ldg(kg + d);
            s_g = fmaf(a1, a1, s_g);
            float b1 = qv - __ldg(kp + d) + 1e-6f;
            s_p = fmaf(b1, b1, s_p);
            float c1 = qv - __ldg(kn + d) + 1e-6f;
            s_n = fmaf(c1, c1, s_n);
        }
        ag = s_g;
        asprd = fmaxf(sqrtf(s_p) - sqrtf(s_n) + 1.0f, 0.0f);
    }
    sg[threadIdx.x] = ag; ss[threadIdx.x] = asprd;
    __syncthreads();
    for (int k = 128; k > 0; k >>= 1) {
        if (threadIdx.x < k) {
            sg[threadIdx.x] += sg[threadIdx.x + k];
            ss[threadIdx.x] += ss[threadIdx.x + k];
        }
        __syncthreads();
    }
    if (threadIdx.x == 0) { g_partG[blockIdx.x] = sg[0]; g_partS[blockIdx.x] = ss[0]; }
}

// ---------------- weight prep: fp32 [oc][c][3][3] -> bf16 hi/lo [tap][oc][c] -
__global__ __launch_bounds__(256) void prep_w_kernel(const float* __restrict__ w,
                                                     int OC, int C, int slot)
{
    int i = blockIdx.x * 256 + threadIdx.x;
    if (i >= OC * C) return;
    int oc = i / C, c = i - oc * C;
    size_t base = (size_t)slot * WSLOT;
    #pragma unroll
    for (int tap = 0; tap < 9; ++tap) {
        float v = w[(size_t)(oc * C + c) * 9 + tap];
        __nv_bfloat16 h = __float2bfloat16(v);
        g_w_hi[base + (size_t)(tap * OC + oc) * C + c] = h;
        g_w_lo[base + (size_t)(tap * OC + oc) * C + c] =
            __float2bfloat16(v - __bfloat162float(h));
    }
}

// ---------------- mma.sync implicit-GEMM 3x3 conv, cp.async pipelined --------
// CTA: 256 out pixels (8 rows x 32 cols) x 64 oc; 8 warps, warp = row x 64 oc.
// Double-buffered: halo A per 32-ch chunk, B per tap, staged via cp.async so
// gmem latency overlaps the MMA burst of the previous iteration. 3-pass split.
template<int C, int OC, int RELU, int FINAL>
__global__ __launch_bounds__(256)
void conv_mma_kernel(const __nv_bfloat16* __restrict__ in_hi,
                     const __nv_bfloat16* __restrict__ in_lo,
                     size_t in_net_stride,
                     __nv_bfloat16* __restrict__ out_hi,
                     __nv_bfloat16* __restrict__ out_lo,
                     float* __restrict__ out_f32_b,
                     float* __restrict__ out_f32_a)
{
    extern __shared__ __align__(16) __nv_bfloat16 smem[];
    // sA[2 buf][2 plane][340][40] = 54400 elems; sB[2 buf][2 plane][64][40] = 10240
    __nv_bfloat16* sA = smem;
    __nv_bfloat16* sB = smem + 54400;

    const int tid  = threadIdx.x;
    const int lane = tid & 31;
    const int wid  = tid >> 5;                // image row within tile
    const int x0 = blockIdx.x * 32;
    const int y0 = blockIdx.y * 8;
    const int net = blockIdx.z / (OC / 64);
    const int obase = (blockIdx.z % (OC / 64)) * 64;

    in_hi += (size_t)net * in_net_stride;
    in_lo += (size_t)net * in_net_stride;
    const size_t wbase = (size_t)net * WSLOT;

    float c_acc[2][8][4];
    #pragma unroll
    for (int i = 0; i < 2; ++i)
        #pragma unroll
        for (int j = 0; j < 8; ++j)
            #pragma unroll
            for (int k = 0; k < 4; ++k) c_acc[i][j][k] = 0.f;

    const int lr = lane & 15, lc = lane >> 4;
    const int bg = lane >> 3, br = lane & 7;

    auto stageA = [&](int c0, int ab) {
        for (int idx = tid; idx < 2720; idx += 256) {
            int plane = idx / 1360;
            int rem = idx - plane * 1360;
            int p = rem >> 2, j = rem & 3;
            int y = y0 + p / 34 - 1;
            int x = x0 + (p - (p / 34) * 34) - 1;
            bool ok = (unsigned)y < (unsigned)HH && (unsigned)x < (unsigned)WWIDTH;
            const __nv_bfloat16* base = plane ? in_lo : in_hi;
            const void* src = ok ? (const void*)(base + (size_t)(y * WWIDTH + x) * C + c0 + j * 8)
                                 : (const void*)base;
            cp16(smem_u32(&sA[ab * 27200 + plane * 13600 + p * 40 + j * 8]), src, ok ? 16 : 0);
        }
    };
    auto stageB = [&](int tap, int c0, int bb) {
        #pragma unroll
        for (int s = 0; s < 2; ++s) {
            int idx = tid + s * 256;
            int plane = idx >> 8;
            int oc = (idx >> 2) & 63;
            int j = idx & 3;
            const __nv_bfloat16* base = plane ? g_w_lo : g_w_hi;
            const void* src = base + wbase + (size_t)(tap * OC + obase + oc) * C + c0 + j * 8;
            cp16(smem_u32(&sB[bb * 5120 + plane * 2560 + oc * 40 + j * 8]), src, 16);
        }
    };

    constexpr int NCH = C / 32;
    constexpr int NI = 9 * NCH;

    // prologue: A(chunk0) then B(iter0), separate groups
    stageA(0, 0); CP_COMMIT();
    stageB(0, 0, 0); CP_COMMIT();

    #pragma unroll 1
    for (int i = 0; i < NI; ++i) {
        const int tap = i % 9, chunk = i / 9;
        const int ky = tap / 3, kx = tap - ky * 3;
        const int abase = (chunk & 1) * 27200;
        const int bbase = (i & 1) * 5120;

        // wait for this iteration's data; allow the chunk's A-prefetch (committed
        // after B at the previous tap-0 iteration) to stay in flight one extra tap.
        if (i > 0 && (i - 1) % 9 == 0) CP_WAIT1(); else CP_WAIT0();
        __syncthreads();

        // issue next iteration's B; at tap 0 also prefetch next chunk's halo A.
        if (i + 1 < NI) {
            int ni = i + 1;
            stageB(ni % 9, (ni / 9) * 32, ni & 1);
        }
        CP_COMMIT();
        if (tap == 0 && chunk + 1 < NCH) { stageA((chunk + 1) * 32, (chunk + 1) & 1); CP_COMMIT(); }

        // compute current tap
        #pragma unroll
        for (int ks = 0; ks < 2; ++ks) {
            uint32_t aH[2][4], aL[2][4];
            #pragma unroll
            for (int ii = 0; ii < 2; ++ii) {
                int hp = (wid + ky) * 34 + ii * 16 + lr + kx;
                ldm_x4(aH[ii], smem_u32(&sA[abase + hp * 40 + ks * 16 + lc * 8]));
                ldm_x4(aL[ii], smem_u32(&sA[abase + 13600 + hp * 40 + ks * 16 + lc * 8]));
            }
            #pragma unroll
            for (int nb = 0; nb < 4; ++nb) {
                uint32_t tH[4], tL[4];
                int row = nb * 16 + (bg >> 1) * 8 + br;
                int col = ks * 16 + (bg & 1) * 8;
                ldm_x4(tH, smem_u32(&sB[bbase + row * 40 + col]));
                ldm_x4(tL, smem_u32(&sB[bbase + 2560 + row * 40 + col]));
                #pragma unroll
                for (int half = 0; half < 2; ++half) {
                    int j = nb * 2 + half;
                    #pragma unroll
                    for (int ii = 0; ii < 2; ++ii) {
                        mma16816(c_acc[ii][j], aH[ii], tH + half * 2);
                        mma16816(c_acc[ii][j], aH[ii], tL + half * 2);
                        mma16816(c_acc[ii][j], aL[ii], tH + half * 2);
                    }
                }
            }
        }
    }

    // ---- epilogue: warp = image row wid; 64 oc x 32 pixels ----
    float* out_f32 = net ? out_f32_a : out_f32_b;
    out_hi += (size_t)net * ((size_t)OC * HWPIX);
    out_lo += (size_t)net * ((size_t)OC * HWPIX);
    const int y = y0 + wid;
    const int q = lane >> 2;
    const int n2 = (lane & 3) * 2;
    if (y < HH) {
        #pragma unroll
        for (int i = 0; i < 2; ++i) {
            #pragma unroll
            for (int j = 0; j < 8; ++j) {
                int oc_l = j * 8 + n2;
                #pragma unroll
                for (int h = 0; h < 2; ++h) {
                    int x = x0 + i * 16 + q + h * 8;
                    if (x < WWIDTH) {
                        float v0 = c_acc[i][j][h * 2 + 0];
                        float v1 = c_acc[i][j][h * 2 + 1];
                        if (RELU) { v0 = fmaxf(v0, 0.f); v1 = fmaxf(v1, 0.f); }
                        int pix = y * WWIDTH + x;
                        int oc = obase + oc_l;
                        if (FINAL) {
                            out_f32[(size_t)oc * HWPIX + pix] = v0;
                            out_f32[(size_t)(oc + 1) * HWPIX + pix] = v1;
                        } else {
                            __nv_bfloat16 h0 = __float2bfloat16(v0);
                            __nv_bfloat16 h1 = __float2bfloat16(v1);
                            __nv_bfloat162 hh; hh.x = h0; hh.y = h1;
                            __nv_bfloat162 ll;
                            ll.x = __float2bfloat16(v0 - __bfloat162float(h0));
                            ll.y = __float2bfloat16(v1 - __bfloat162float(h1));
                            *(__nv_bfloat162*)&out_hi[(size_t)pix * OC + oc] = hh;
                            *(__nv_bfloat162*)&out_lo[(size_t)pix * OC + oc] = ll;
                        }
                    }
                }
            }
        }
    }
}

// ---------------- attention mask + cfeature ----------------------------------
__global__ __launch_bounds__(256) void atten_kernel(float* __restrict__ outcf)
{
    int p = blockIdx.x * 256 + threadIdx.x;
    if (p >= HWPIX) return;
    float num = 0.f, na = 0.f, nb = 0.f;
    #pragma unroll 4
    for (int c = 0; c < 64; ++c) {
        float a = g_av[c * HWPIX + p];
        float b = g_bv[c * HWPIX + p];
        num = fmaf(a, b, num);
        na  = fmaf(a, a, na);
        nb  = fmaf(b, b, nb);
    }
    float mask = num / fmaxf(sqrtf(na) * sqrtf(nb), 1e-6f);
    #pragma unroll 4
    for (int c = 0; c < DDIM; ++c)
        outcf[c * HWPIX + p] = mask * g_qn[c * HWPIX + p];
}

// ---------------- scalar outputs ---------------------------------------------
__global__ void finalize_kernel(float* __restrict__ out)
{
    if (threadIdx.x == 0 && blockIdx.x == 0) {
        float sg = 0.f, ss = 0.f;
        for (int i = 0; i < NBLK_PIX; ++i) { sg += g_partG[i]; ss += g_partS[i]; }
        out[(size_t)MKEYS * DDIM + (size_t)DDIM * HWPIX + 0] = sg / ((float)HWPIX * (float)DDIM);
        out[(size_t)MKEYS * DDIM + (size_t)DDIM * HWPIX + 1] = ss / (float)HWPIX;
    }
}

// ---------------- launch -----------------------------------------------------
#define CONV_SMEM (129280)   // (54400 + 10240) elems * 2 bytes

extern "C" void kernel_launch(void* const* d_in, const int* in_sizes, int n_in,
                              void* d_out, int out_size)
{
    const float* query = (const float*)d_in[0];
    const float* keys  = (const float*)d_in[1];
    const float* t_w1  = (const float*)d_in[2];
    const float* t_w2  = (const float*)d_in[3];
    const float* t_w3  = (const float*)d_in[4];
    const float* t_w4  = (const float*)d_in[5];
    const float* k_w1  = (const float*)d_in[6];
    const float* k_w2  = (const float*)d_in[7];
    const float* k_w3  = (const float*)d_in[8];
    const float* k_w4  = (const float*)d_in[9];
    float* out = (float*)d_out;

    __nv_bfloat16 *p_qh, *p_ql, *p_h1h, *p_h1l, *p_h2h, *p_h2l, *p_h3h, *p_h3l;
    float *p_av, *p_bv;
    cudaGetSymbolAddress((void**)&p_qh,  g_q_hi);
    cudaGetSymbolAddress((void**)&p_ql,  g_q_lo);
    cudaGetSymbolAddress((void**)&p_h1h, g_h1_hi);
    cudaGetSymbolAddress((void**)&p_h1l, g_h1_lo);
    cudaGetSymbolAddress((void**)&p_h2h, g_h2_hi);
    cudaGetSymbolAddress((void**)&p_h2l, g_h2_lo);
    cudaGetSymbolAddress((void**)&p_h3h, g_h3_hi);
    cudaGetSymbolAddress((void**)&p_h3l, g_h3_lo);
    cudaGetSymbolAddress((void**)&p_av,  g_av);
    cudaGetSymbolAddress((void**)&p_bv,  g_bv);

    cudaFuncSetAttribute(conv_mma_kernel<128, 512, 1, 0>,
                         cudaFuncAttributeMaxDynamicSharedMemorySize, CONV_SMEM);
    cudaFuncSetAttribute(conv_mma_kernel<512, 256, 1, 0>,
                         cudaFuncAttributeMaxDynamicSharedMemorySize, CONV_SMEM);
    cudaFuncSetAttribute(conv_mma_kernel<256, 128, 1, 0>,
                         cudaFuncAttributeMaxDynamicSharedMemorySize, CONV_SMEM);
    cudaFuncSetAttribute(conv_mma_kernel<128, 64, 0, 1>,
                         cudaFuncAttributeMaxDynamicSharedMemorySize, CONV_SMEM);

    // Fork a side stream for the (independent) score/loss branch so it
    // overlaps with the tensor-bound conv branch (graph-capture fork pattern).
    cudaStream_t s2;
    cudaStreamCreateWithFlags(&s2, cudaStreamNonBlocking);
    cudaEvent_t ev_q, ev_score;
    cudaEventCreateWithFlags(&ev_q, cudaEventDisableTiming);
    cudaEventCreateWithFlags(&ev_score, cudaEventDisableTiming);

    // updated_memory = keys (unchanged)
    cudaMemcpyAsync(out, keys, (size_t)MKEYS * DDIM * sizeof(float),
                    cudaMemcpyDeviceToDevice, 0);

    qnorm_kernel<<<NBLK_PIX, 256>>>(query);
    cudaEventRecord(ev_q, 0);
    cudaStreamWaitEvent(s2, ev_q, 0);

    // ---- score branch on s2 ----
    keynorm_kernel<<<MKEYS / 8, 256, 0, s2>>>(keys);
    score_mma_kernel<<<dim3((HWPIX + 63) / 64, MKEYS / 128), 256, 0, s2>>>();
    rowsum_kernel<<<MKEYS, 256, 0, s2>>>();
    top2_kernel<<<NBLK_PIX, 256, 0, s2>>>();
    loss_kernel<<<NBLK_PIX, 256, 0, s2>>>(keys);
    cudaEventRecord(ev_score, s2);

    // ---- conv branch on main stream ----
    const size_t S1 = (size_t)512 * HWPIX;
    const size_t S2b = (size_t)256 * HWPIX;
    const size_t S3 = (size_t)128 * HWPIX;

    prep_w_kernel<<<(512 * 128 + 255) / 256, 256>>>(t_w1, 512, 128, 0);
    prep_w_kernel<<<(512 * 128 + 255) / 256, 256>>>(k_w1, 512, 128, 1);
    conv_mma_kernel<128, 512, 1, 0><<<dim3(10, 19, 16), 256, CONV_SMEM>>>(
        p_qh, p_ql, 0, p_h1h, p_h1l, nullptr, nullptr);
    prep_w_kernel<<<(256 * 512 + 255) / 256, 256>>>(t_w2, 256, 512, 0);
    prep_w_kernel<<<(256 * 512 + 255) / 256, 256>>>(k_w2, 256, 512, 1);
    conv_mma_kernel<512, 256, 1, 0><<<dim3(10, 19, 8), 256, CONV_SMEM>>>(
        p_h1h, p_h1l, S1, p_h2h, p_h2l, nullptr, nullptr);
    prep_w_kernel<<<(128 * 256 + 255) / 256, 256>>>(t_w3, 128, 256, 0);
    prep_w_kernel<<<(128 * 256 + 255) / 256, 256>>>(k_w3, 128, 256, 1);
    conv_mma_kernel<256, 128, 1, 0><<<dim3(10, 19, 4), 256, CONV_SMEM>>>(
        p_h2h, p_h2l, S2b, p_h3h, p_h3l, nullptr, nullptr);
    prep_w_kernel<<<(64 * 128 + 255) / 256, 256>>>(t_w4, 64, 128, 0);
    prep_w_kernel<<<(64 * 128 + 255) / 256, 256>>>(k_w4, 64, 128, 1);
    conv_mma_kernel<128, 64, 0, 1><<<dim3(10, 19, 2), 256, CONV_SMEM>>>(
        p_h3h, p_h3l, S3, nullptr, nullptr, p_bv, p_av);

    atten_kernel<<<NBLK_PIX, 256>>>(out + (size_t)MKEYS * DDIM);

    // ---- join: finalize needs loss partials from s2 ----
    cudaStreamWaitEvent(0, ev_score, 0);
    finalize_kernel<<<1, 1>>>(out);
}

// round 13
// speedup vs baseline: 1.3624x; 1.3624x over previous
#include <cuda_runtime.h>
#include <cuda_bf16.h>
#include <cuda_fp16.h>
#include <math.h>
#include <stdint.h>

#define HH      148
#define WWIDTH  300
#define HWPIX   44400      // 148*300
#define DDIM    128
#define MKEYS   2048
#define NBLK_PIX 174       // ceil(44400/256)
#define WSLOT   1179648    // max weight elems per net slot (256*512*9)

// ---------------- scratch (device globals; no allocation allowed) -----------
__device__ float g_qn[DDIM * HWPIX];          // normalized query, planar [c][p]
__device__ float g_qnn[HWPIX];
__device__ float g_mn[MKEYS];
__device__ float g_cos[(size_t)MKEYS * HWPIX];// 364 MB
__device__ float g_L[MKEYS];
__device__ int   g_i1[HWPIX];
__device__ int   g_i2[HWPIX];
__device__ float g_av[64 * HWPIX];            // a = theta_net(qn, k_w*), planar
__device__ float g_bv[64 * HWPIX];            // b = theta_net(qn, t_w*), planar
__device__ float g_partG[NBLK_PIX];
__device__ float g_partS[NBLK_PIX];

// score path: bf16 3-pass split (unchanged)
__device__ __nv_bfloat16 g_q_hi[(size_t)DDIM * HWPIX];
__device__ __nv_bfloat16 g_q_lo[(size_t)DDIM * HWPIX];
__device__ __nv_bfloat16 g_k_hi[MKEYS * DDIM];
__device__ __nv_bfloat16 g_k_lo[MKEYS * DDIM];

// conv path: fp16 2-pass split — activations hi+lo, weights hi only
__device__ __half g_qf_hi[(size_t)DDIM * HWPIX];
__device__ __half g_qf_lo[(size_t)DDIM * HWPIX];
__device__ __half g_h1_hi[(size_t)2 * 512 * HWPIX];
__device__ __half g_h1_lo[(size_t)2 * 512 * HWPIX];
__device__ __half g_h2_hi[(size_t)2 * 256 * HWPIX];
__device__ __half g_h2_lo[(size_t)2 * 256 * HWPIX];
__device__ __half g_h3_hi[(size_t)2 * 128 * HWPIX];
__device__ __half g_h3_lo[(size_t)2 * 128 * HWPIX];
__device__ __half g_w_h[(size_t)2 * WSLOT];   // [net][tap][oc][c], hi only

// ---------------- warp MMA helpers (baseline PTX, sm_80+) --------------------
__device__ __forceinline__ uint32_t smem_u32(const void* p) {
    uint32_t a;
    asm("{ .reg .u64 t; cvta.to.shared.u64 t, %1; cvt.u32.u64 %0, t; }"
        : "=r"(a) : "l"(p));
    return a;
}
__device__ __forceinline__ void ldm_x4(uint32_t* r, uint32_t addr) {
    asm volatile("ldmatrix.sync.aligned.m8n8.x4.shared.b16 {%0,%1,%2,%3}, [%4];"
                 : "=r"(r[0]), "=r"(r[1]), "=r"(r[2]), "=r"(r[3]) : "r"(addr));
}
__device__ __forceinline__ void mma_bf16(float* d, const uint32_t* a, const uint32_t* b) {
    asm volatile("mma.sync.aligned.m16n8k16.row.col.f32.bf16.bf16.f32 "
                 "{%0,%1,%2,%3}, {%4,%5,%6,%7}, {%8,%9}, {%0,%1,%2,%3};"
                 : "+f"(d[0]), "+f"(d[1]), "+f"(d[2]), "+f"(d[3])
                 : "r"(a[0]), "r"(a[1]), "r"(a[2]), "r"(a[3]),
                   "r"(b[0]), "r"(b[1]));
}
__device__ __forceinline__ void mma_f16(float* d, const uint32_t* a, const uint32_t* b) {
    asm volatile("mma.sync.aligned.m16n8k16.row.col.f32.f16.f16.f32 "
                 "{%0,%1,%2,%3}, {%4,%5,%6,%7}, {%8,%9}, {%0,%1,%2,%3};"
                 : "+f"(d[0]), "+f"(d[1]), "+f"(d[2]), "+f"(d[3])
                 : "r"(a[0]), "r"(a[1]), "r"(a[2]), "r"(a[3]),
                   "r"(b[0]), "r"(b[1]));
}

// ---------------- query normalize --------------------------------------------
__global__ __launch_bounds__(256) void qnorm_kernel(const float* __restrict__ q)
{
    int p = blockIdx.x * 256 + threadIdx.x;
    if (p >= HWPIX) return;
    float s = 0.f;
    #pragma unroll 4
    for (int c = 0; c < DDIM; ++c) { float v = q[c * HWPIX + p]; s = fmaf(v, v, s); }
    float r = sqrtf(s);
    float inv = 1.f / fmaxf(r, 1e-12f);
    #pragma unroll 4
    for (int c = 0; c < DDIM; ++c) {
        float v = q[c * HWPIX + p] * inv;
        g_qn[c * HWPIX + p] = v;
        __nv_bfloat16 h = __float2bfloat16(v);
        g_q_hi[(size_t)p * DDIM + c] = h;
        g_q_lo[(size_t)p * DDIM + c] = __float2bfloat16(v - __bfloat162float(h));
        __half hf = __float2half(v);
        g_qf_hi[(size_t)p * DDIM + c] = hf;
        g_qf_lo[(size_t)p * DDIM + c] = __float2half(v - __half2float(hf));
    }
    g_qnn[p] = r * inv;
}

// ---------------- key norms + bf16 split -------------------------------------
__global__ void keynorm_kernel(const float* __restrict__ keys)
{
    int m = blockIdx.x * 8 + (threadIdx.x >> 5);
    int lane = threadIdx.x & 31;
    float s = 0.f;
    for (int j = lane; j < DDIM; j += 32) {
        float v = keys[m * DDIM + j];
        s = fmaf(v, v, s);
        __nv_bfloat16 h = __float2bfloat16(v);
        g_k_hi[m * DDIM + j] = h;
        g_k_lo[m * DDIM + j] = __float2bfloat16(v - __bfloat162float(h));
    }
    #pragma unroll
    for (int o = 16; o > 0; o >>= 1) s += __shfl_xor_sync(0xffffffffu, s, o);
    if (lane == 0) g_mn[m] = sqrtf(s);
}

// ---------------- score GEMM via mma.sync (3-pass bf16 split) ----------------
__global__ __launch_bounds__(256) void score_mma_kernel()
{
    __shared__ __align__(16) __nv_bfloat16 sA[2][128][40];
    __shared__ __align__(16) __nv_bfloat16 sB[2][64][40];

    const int tid  = threadIdx.x;
    const int lane = tid & 31;
    const int wid  = tid >> 5;
    const int warpM = wid & 3;
    const int warpN = wid >> 2;
    const int m0 = blockIdx.y * 128;
    const int n0 = blockIdx.x * 64;

    float c_acc[2][4][4];
    #pragma unroll
    for (int i = 0; i < 2; ++i)
        #pragma unroll
        for (int j = 0; j < 4; ++j)
            #pragma unroll
            for (int k = 0; k < 4; ++k) c_acc[i][j][k] = 0.f;

    const int lr = lane & 15, lc = lane >> 4;
    const int bg = lane >> 3, br = lane & 7;

    for (int ch = 0; ch < 4; ++ch) {
        const int c0 = ch * 32;
        if (ch) __syncthreads();
        #pragma unroll
        for (int s = 0; s < 4; ++s) {
            int idx = tid + s * 256;
            int plane = idx >> 9;
            int m = (idx >> 2) & 127;
            int j = idx & 3;
            uint4 v = *(const uint4*)((plane ? g_k_lo : g_k_hi) +
                                      (size_t)(m0 + m) * DDIM + c0 + j * 8);
            *(uint4*)&sA[plane][m][j * 8] = v;
        }
        #pragma unroll
        for (int s = 0; s < 2; ++s) {
            int idx = tid + s * 256;
            int plane = idx >> 8;
            int n = (idx >> 2) & 63;
            int j = idx & 3;
            uint4 v = make_uint4(0u, 0u, 0u, 0u);
            if (n0 + n < HWPIX)
                v = *(const uint4*)((plane ? g_q_lo : g_q_hi) +
                                    (size_t)(n0 + n) * DDIM + c0 + j * 8);
            *(uint4*)&sB[plane][n][j * 8] = v;
        }
        __syncthreads();

        #pragma unroll
        for (int ks = 0; ks < 2; ++ks) {
            uint32_t aH[2][4], aL[2][4];
            #pragma unroll
            for (int i = 0; i < 2; ++i) {
                ldm_x4(aH[i], smem_u32(&sA[0][warpM * 32 + i * 16 + lr][ks * 16 + lc * 8]));
                ldm_x4(aL[i], smem_u32(&sA[1][warpM * 32 + i * 16 + lr][ks * 16 + lc * 8]));
            }
            uint32_t bH[4][2], bL[4][2];
            #pragma unroll
            for (int nb = 0; nb < 2; ++nb) {
                uint32_t t4[4];
                int row = warpN * 32 + nb * 16 + (bg >> 1) * 8 + br;
                int col = ks * 16 + (bg & 1) * 8;
                ldm_x4(t4, smem_u32(&sB[0][row][col]));
                bH[nb * 2][0] = t4[0]; bH[nb * 2][1] = t4[1];
                bH[nb * 2 + 1][0] = t4[2]; bH[nb * 2 + 1][1] = t4[3];
                ldm_x4(t4, smem_u32(&sB[1][row][col]));
                bL[nb * 2][0] = t4[0]; bL[nb * 2][1] = t4[1];
                bL[nb * 2 + 1][0] = t4[2]; bL[nb * 2 + 1][1] = t4[3];
            }
            #pragma unroll
            for (int i = 0; i < 2; ++i)
                #pragma unroll
                for (int j = 0; j < 4; ++j) {
                    mma_bf16(c_acc[i][j], aH[i], bH[j]);
                    mma_bf16(c_acc[i][j], aH[i], bL[j]);
                    mma_bf16(c_acc[i][j], aL[i], bH[j]);
                }
        }
    }

    const int q = lane >> 2;
    const int n2 = (lane & 3) * 2;
    #pragma unroll
    for (int i = 0; i < 2; ++i) {
        #pragma unroll
        for (int h = 0; h < 2; ++h) {
            int m = m0 + warpM * 32 + i * 16 + q + h * 8;
            float mnv = __ldg(&g_mn[m]);
            #pragma unroll
            for (int j = 0; j < 4; ++j) {
                int n = n0 + warpN * 32 + j * 8 + n2;
                if (n < HWPIX) {
                    float q0 = __ldg(&g_qnn[n]);
                    float q1 = __ldg(&g_qnn[n + 1]);
                    float2 w;
                    w.x = c_acc[i][j][h * 2 + 0] / fmaxf(mnv * q0, 1e-6f);
                    w.y = c_acc[i][j][h * 2 + 1] / fmaxf(mnv * q1, 1e-6f);
                    *(float2*)&g_cos[(size_t)m * HWPIX + n] = w;
                }
            }
        }
    }
}

// ---------------- per-row logsumexp ------------------------------------------
__global__ __launch_bounds__(256) void rowsum_kernel()
{
    __shared__ float sred[256];
    const float* cp = g_cos + (size_t)blockIdx.x * HWPIX;
    float s = 0.f;
    for (int n = threadIdx.x; n < HWPIX; n += 256) s += expf(cp[n]);
    sred[threadIdx.x] = s;
    __syncthreads();
    for (int k = 128; k > 0; k >>= 1) {
        if (threadIdx.x < k) sred[threadIdx.x] += sred[threadIdx.x + k];
        __syncthreads();
    }
    if (threadIdx.x == 0) g_L[blockIdx.x] = logf(sred[0]);
}

// ---------------- per-pixel top-2 of (cos[m,n] - L[m]) -----------------------
__global__ __launch_bounds__(256) void top2_kernel()
{
    __shared__ float sL[MKEYS];
    for (int i = threadIdx.x; i < MKEYS; i += 256) sL[i] = g_L[i];
    __syncthreads();
    int n = blockIdx.x * 256 + threadIdx.x;
    if (n >= HWPIX) return;
    float v1 = -1e30f, v2 = -1e30f;
    int i1 = 0, i2 = 0;
    const float* cp = g_cos + n;
    #pragma unroll 4
    for (int m = 0; m < MKEYS; ++m) {
        float s = cp[(size_t)m * HWPIX] - sL[m];
        if (s > v1)      { v2 = v1; i2 = i1; v1 = s; i1 = m; }
        else if (s > v2) { v2 = s; i2 = m; }
    }
    g_i1[n] = i1;
    g_i2[n] = i2;
}

// ---------------- losses (with reference's top2.T.reshape scrambling) --------
__global__ __launch_bounds__(256) void loss_kernel(const float* __restrict__ keys)
{
    __shared__ float sg[256], ss[256];
    int n = blockIdx.x * 256 + threadIdx.x;
    float ag = 0.f, asprd = 0.f;
    if (n < HWPIX) {
        int gi = g_i1[n];
        int pos_idx, neg_idx;
        if (n < HWPIX / 2) {
            pos_idx = g_i1[2 * n];
            neg_idx = g_i1[2 * n + 1];
        } else {
            int m2 = n - HWPIX / 2;
            pos_idx = g_i2[2 * m2];
            neg_idx = g_i2[2 * m2 + 1];
        }
        const float* kg = keys + (size_t)gi * DDIM;
        const float* kp = keys + (size_t)pos_idx * DDIM;
        const float* kn = keys + (size_t)neg_idx * DDIM;
        float s_g = 0.f, s_p = 0.f, s_n = 0.f;
        #pragma unroll 4
        for (int d = 0; d < DDIM; ++d) {
            float qv = g_qn[d * HWPIX + n];
            float a1 = qv - __ldg(kg + d);
            s_g = fmaf(a1, a1, s_g);
            float b1 = qv - __ldg(kp + d) + 1e-6f;
            s_p = fmaf(b1, b1, s_p);
            float c1 = qv - __ldg(kn + d) + 1e-6f;
            s_n = fmaf(c1, c1, s_n);
        }
        ag = s_g;
        asprd = fmaxf(sqrtf(s_p) - sqrtf(s_n) + 1.0f, 0.0f);
    }
    sg[threadIdx.x] = ag; ss[threadIdx.x] = asprd;
    __syncthreads();
    for (int k = 128; k > 0; k >>= 1) {
        if (threadIdx.x < k) {
            sg[threadIdx.x] += sg[threadIdx.x + k];
            ss[threadIdx.x] += ss[threadIdx.x + k];
        }
        __syncthreads();
    }
    if (threadIdx.x == 0) { g_partG[blockIdx.x] = sg[0]; g_partS[blockIdx.x] = ss[0]; }
}

// ---------------- weight prep: fp32 [oc][c][3][3] -> fp16 [tap][oc][c] -------
__global__ __launch_bounds__(256) void prep_w_kernel(const float* __restrict__ w,
                                                     int OC, int C, int slot)
{
    int i = blockIdx.x * 256 + threadIdx.x;
    if (i >= OC * C) return;
    int oc = i / C, c = i - oc * C;
    size_t base = (size_t)slot * WSLOT;
    #pragma unroll
    for (int tap = 0; tap < 9; ++tap) {
        float v = w[(size_t)(oc * C + c) * 9 + tap];
        g_w_h[base + (size_t)(tap * OC + oc) * C + c] = __float2half(v);
    }
}

// ---------------- mma.sync implicit-GEMM 3x3 conv, fp16 2-pass ---------------
// CTA: 256 out pixels (8 rows x 32 cols) x 64 oc; 8 warps, warp = row x 64 oc.
// Halo (10x34) staged once per 32-ch chunk. 2-pass fp16 split:
//   x*w = (xh + xl)*wh  exactly; dropped term x*wl ~ 2^-11 relative.
template<int C, int OC, int RELU, int FINAL>
__global__ __launch_bounds__(256)
void conv_mma_kernel(const __half* __restrict__ in_hi,
                     const __half* __restrict__ in_lo,
                     size_t in_net_stride,
                     __half* __restrict__ out_hi,
                     __half* __restrict__ out_lo,
                     float* __restrict__ out_f32_b,
                     float* __restrict__ out_f32_a)
{
    extern __shared__ __align__(16) __half smem[];
    // sA[2 plane][340][40] = 27200 elems; sB[64][40] = 2560 elems
    __half* sA = smem;                 // plane*13600 + p*40 + k
    __half* sB = smem + 27200;         // oc*40 + k

    const int tid  = threadIdx.x;
    const int lane = tid & 31;
    const int wid  = tid >> 5;                // image row within tile
    const int x0 = blockIdx.x * 32;
    const int y0 = blockIdx.y * 8;
    const int net = blockIdx.z / (OC / 64);
    const int obase = (blockIdx.z % (OC / 64)) * 64;

    in_hi += (size_t)net * in_net_stride;
    in_lo += (size_t)net * in_net_stride;
    const size_t wbase = (size_t)net * WSLOT;

    float c_acc[2][8][4];
    #pragma unroll
    for (int i = 0; i < 2; ++i)
        #pragma unroll
        for (int j = 0; j < 8; ++j)
            #pragma unroll
            for (int k = 0; k < 4; ++k) c_acc[i][j][k] = 0.f;

    const int lr = lane & 15, lc = lane >> 4;
    const int bg = lane >> 3, br = lane & 7;

    for (int c0 = 0; c0 < C; c0 += 32) {
        __syncthreads();   // previous chunk's ldmatrix reads of sA done
        // ---- stage halo A: 340 pixels (10x34) x 32 ch, hi+lo (2720 jobs) ----
        for (int idx = tid; idx < 2720; idx += 256) {
            int plane = idx / 1360;
            int rem = idx - plane * 1360;
            int p = rem >> 2;
            int j = rem & 3;
            int y = y0 + p / 34 - 1;
            int x = x0 + (p - (p / 34) * 34) - 1;
            uint4 v = make_uint4(0u, 0u, 0u, 0u);
            if ((unsigned)y < (unsigned)HH && (unsigned)x < (unsigned)WWIDTH)
                v = *(const uint4*)((plane ? in_lo : in_hi) +
                                    (size_t)(y * WWIDTH + x) * C + c0 + j * 8);
            *(uint4*)&sA[plane * 13600 + p * 40 + j * 8] = v;
        }

        #pragma unroll 1
        for (int tap = 0; tap < 9; ++tap) {
            const int ky = tap / 3, kx = tap - ky * 3;
            if (tap) __syncthreads();   // previous tap's sB reads done
            // ---- stage B: 64 oc x 32 ch (hi only), 256 x 16B jobs ----
            {
                int oc = tid >> 2;
                int j = tid & 3;
                uint4 v = *(const uint4*)(g_w_h + wbase +
                                          (size_t)(tap * OC + obase + oc) * C + c0 + j * 8);
                *(uint4*)&sB[oc * 40 + j * 8] = v;
            }
            __syncthreads();

            #pragma unroll
            for (int ks = 0; ks < 2; ++ks) {
                uint32_t aH[2][4], aL[2][4];
                #pragma unroll
                for (int i = 0; i < 2; ++i) {
                    int hp = (wid + ky) * 34 + i * 16 + lr + kx;
                    ldm_x4(aH[i], smem_u32(&sA[hp * 40 + ks * 16 + lc * 8]));
                    ldm_x4(aL[i], smem_u32(&sA[13600 + hp * 40 + ks * 16 + lc * 8]));
                }
                #pragma unroll
                for (int nb = 0; nb < 4; ++nb) {
                    uint32_t tH[4];
                    int row = nb * 16 + (bg >> 1) * 8 + br;
                    int col = ks * 16 + (bg & 1) * 8;
                    ldm_x4(tH, smem_u32(&sB[row * 40 + col]));
                    #pragma unroll
                    for (int half = 0; half < 2; ++half) {
                        int j = nb * 2 + half;
                        #pragma unroll
                        for (int i = 0; i < 2; ++i) {
                            mma_f16(c_acc[i][j], aH[i], tH + half * 2);
                            mma_f16(c_acc[i][j], aL[i], tH + half * 2);
                        }
                    }
                }
            }
        }
    }

    // ---- epilogue: warp = image row wid; 64 oc x 32 pixels ----
    float* out_f32 = net ? out_f32_a : out_f32_b;
    out_hi += (size_t)net * ((size_t)OC * HWPIX);
    out_lo += (size_t)net * ((size_t)OC * HWPIX);
    const int y = y0 + wid;
    const int q = lane >> 2;
    const int n2 = (lane & 3) * 2;
    if (y < HH) {
        #pragma unroll
        for (int i = 0; i < 2; ++i) {
            #pragma unroll
            for (int j = 0; j < 8; ++j) {
                int oc_l = j * 8 + n2;
                #pragma unroll
                for (int h = 0; h < 2; ++h) {
                    int x = x0 + i * 16 + q + h * 8;
                    if (x < WWIDTH) {
                        float v0 = c_acc[i][j][h * 2 + 0];
                        float v1 = c_acc[i][j][h * 2 + 1];
                        if (RELU) { v0 = fmaxf(v0, 0.f); v1 = fmaxf(v1, 0.f); }
                        int pix = y * WWIDTH + x;
                        int oc = obase + oc_l;
                        if (FINAL) {
                            out_f32[(size_t)oc * HWPIX + pix] = v0;
                            out_f32[(size_t)(oc + 1) * HWPIX + pix] = v1;
                        } else {
                            __half h0 = __float2half(v0);
                            __half h1 = __float2half(v1);
                            __half2 hh; hh.x = h0; hh.y = h1;
                            __half2 ll;
                            ll.x = __float2half(v0 - __half2float(h0));
                            ll.y = __float2half(v1 - __half2float(h1));
                            *(__half2*)&out_hi[(size_t)pix * OC + oc] = hh;
                            *(__half2*)&out_lo[(size_t)pix * OC + oc] = ll;
                        }
                    }
                }
            }
        }
    }
}

// ---------------- attention mask + cfeature ----------------------------------
__global__ __launch_bounds__(256) void atten_kernel(float* __restrict__ outcf)
{
    int p = blockIdx.x * 256 + threadIdx.x;
    if (p >= HWPIX) return;
    float num = 0.f, na = 0.f, nb = 0.f;
    #pragma unroll 4
    for (int c = 0; c < 64; ++c) {
        float a = g_av[c * HWPIX + p];
        float b = g_bv[c * HWPIX + p];
        num = fmaf(a, b, num);
        na  = fmaf(a, a, na);
        nb  = fmaf(b, b, nb);
    }
    float mask = num / fmaxf(sqrtf(na) * sqrtf(nb), 1e-6f);
    #pragma unroll 4
    for (int c = 0; c < DDIM; ++c)
        outcf[c * HWPIX + p] = mask * g_qn[c * HWPIX + p];
}

// ---------------- scalar outputs ---------------------------------------------
__global__ void finalize_kernel(float* __restrict__ out)
{
    if (threadIdx.x == 0 && blockIdx.x == 0) {
        float sg = 0.f, ss = 0.f;
        for (int i = 0; i < NBLK_PIX; ++i) { sg += g_partG[i]; ss += g_partS[i]; }
        out[(size_t)MKEYS * DDIM + (size_t)DDIM * HWPIX + 0] = sg / ((float)HWPIX * (float)DDIM);
        out[(size_t)MKEYS * DDIM + (size_t)DDIM * HWPIX + 1] = ss / (float)HWPIX;
    }
}

// ---------------- launch -----------------------------------------------------
#define CONV_SMEM (59520)   // (27200 + 2560) elems * 2 bytes

extern "C" void kernel_launch(void* const* d_in, const int* in_sizes, int n_in,
                              void* d_out, int out_size)
{
    const float* query = (const float*)d_in[0];
    const float* keys  = (const float*)d_in[1];
    const float* t_w1  = (const float*)d_in[2];
    const float* t_w2  = (const float*)d_in[3];
    const float* t_w3  = (const float*)d_in[4];
    const float* t_w4  = (const float*)d_in[5];
    const float* k_w1  = (const float*)d_in[6];
    const float* k_w2  = (const float*)d_in[7];
    const float* k_w3  = (const float*)d_in[8];
    const float* k_w4  = (const float*)d_in[9];
    float* out = (float*)d_out;

    __half *p_qfh, *p_qfl, *p_h1h, *p_h1l, *p_h2h, *p_h2l, *p_h3h, *p_h3l;
    float *p_av, *p_bv;
    cudaGetSymbolAddress((void**)&p_qfh, g_qf_hi);
    cudaGetSymbolAddress((void**)&p_qfl, g_qf_lo);
    cudaGetSymbolAddress((void**)&p_h1h, g_h1_hi);
    cudaGetSymbolAddress((void**)&p_h1l, g_h1_lo);
    cudaGetSymbolAddress((void**)&p_h2h, g_h2_hi);
    cudaGetSymbolAddress((void**)&p_h2l, g_h2_lo);
    cudaGetSymbolAddress((void**)&p_h3h, g_h3_hi);
    cudaGetSymbolAddress((void**)&p_h3l, g_h3_lo);
    cudaGetSymbolAddress((void**)&p_av,  g_av);
    cudaGetSymbolAddress((void**)&p_bv,  g_bv);

    cudaFuncSetAttribute(conv_mma_kernel<128, 512, 1, 0>,
                         cudaFuncAttributeMaxDynamicSharedMemorySize, CONV_SMEM);
    cudaFuncSetAttribute(conv_mma_kernel<512, 256, 1, 0>,
                         cudaFuncAttributeMaxDynamicSharedMemorySize, CONV_SMEM);
    cudaFuncSetAttribute(conv_mma_kernel<256, 128, 1, 0>,
                         cudaFuncAttributeMaxDynamicSharedMemorySize, CONV_SMEM);
    cudaFuncSetAttribute(conv_mma_kernel<128, 64, 0, 1>,
                         cudaFuncAttributeMaxDynamicSharedMemorySize, CONV_SMEM);

    // Fork a side stream for the (independent) score/loss branch so it
    // overlaps with the tensor-bound conv branch (graph-capture fork pattern).
    cudaStream_t s2;
    cudaStreamCreateWithFlags(&s2, cudaStreamNonBlocking);
    cudaEvent_t ev_q, ev_score;
    cudaEventCreateWithFlags(&ev_q, cudaEventDisableTiming);
    cudaEventCreateWithFlags(&ev_score, cudaEventDisableTiming);

    // updated_memory = keys (unchanged)
    cudaMemcpyAsync(out, keys, (size_t)MKEYS * DDIM * sizeof(float),
                    cudaMemcpyDeviceToDevice, 0);

    qnorm_kernel<<<NBLK_PIX, 256>>>(query);
    cudaEventRecord(ev_q, 0);
    cudaStreamWaitEvent(s2, ev_q, 0);

    // ---- score branch on s2 ----
    keynorm_kernel<<<MKEYS / 8, 256, 0, s2>>>(keys);
    score_mma_kernel<<<dim3((HWPIX + 63) / 64, MKEYS / 128), 256, 0, s2>>>();
    rowsum_kernel<<<MKEYS, 256, 0, s2>>>();
    top2_kernel<<<NBLK_PIX, 256, 0, s2>>>();
    loss_kernel<<<NBLK_PIX, 256, 0, s2>>>(keys);
    cudaEventRecord(ev_score, s2);

    // ---- conv branch on main stream ----
    const size_t S1 = (size_t)512 * HWPIX;
    const size_t S2b = (size_t)256 * HWPIX;
    const size_t S3 = (size_t)128 * HWPIX;

    prep_w_kernel<<<(512 * 128 + 255) / 256, 256>>>(t_w1, 512, 128, 0);
    prep_w_kernel<<<(512 * 128 + 255) / 256, 256>>>(k_w1, 512, 128, 1);
    conv_mma_kernel<128, 512, 1, 0><<<dim3(10, 19, 16), 256, CONV_SMEM>>>(
        p_qfh, p_qfl, 0, p_h1h, p_h1l, nullptr, nullptr);
    prep_w_kernel<<<(256 * 512 + 255) / 256, 256>>>(t_w2, 256, 512, 0);
    prep_w_kernel<<<(256 * 512 + 255) / 256, 256>>>(k_w2, 256, 512, 1);
    conv_mma_kernel<512, 256, 1, 0><<<dim3(10, 19, 8), 256, CONV_SMEM>>>(
        p_h1h, p_h1l, S1, p_h2h, p_h2l, nullptr, nullptr);
    prep_w_kernel<<<(128 * 256 + 255) / 256, 256>>>(t_w3, 128, 256, 0);
    prep_w_kernel<<<(128 * 256 + 255) / 256, 256>>>(k_w3, 128, 256, 1);
    conv_mma_kernel<256, 128, 1, 0><<<dim3(10, 19, 4), 256, CONV_SMEM>>>(
        p_h2h, p_h2l, S2b, p_h3h, p_h3l, nullptr, nullptr);
    prep_w_kernel<<<(64 * 128 + 255) / 256, 256>>>(t_w4, 64, 128, 0);
    prep_w_kernel<<<(64 * 128 + 255) / 256, 256>>>(k_w4, 64, 128, 1);
    conv_mma_kernel<128, 64, 0, 1><<<dim3(10, 19, 2), 256, CONV_SMEM>>>(
        p_h3h, p_h3l, S3, nullptr, nullptr, p_bv, p_av);

    atten_kernel<<<NBLK_PIX, 256>>>(out + (size_t)MKEYS * DDIM);

    // ---- join: finalize needs loss partials from s2 ----
    cudaStreamWaitEvent(0, ev_score, 0);
    finalize_kernel<<<1, 1>>>(out);
}